// round 17
// baseline (speedup 1.0000x reference)
#include <cuda_runtime.h>
#include <cuda_fp16.h>
#include <cuda_bf16.h>
#include <cuda_pipeline.h>

#define DPAR   1024
#define KSEL   32
#define NITER  4
#define CHUNKS 8          // 8 x float4 per lane = 32 elements/lane
#define H2N    16         // 16 half2 = 32 z values per lane
#define WPB    8          // warps (rows) per block

// tanh-form GELU using HW tanh.approx.f32 (MUFU.TANH).
// gelu(x) = 0.5*x*(1 + tanh(x*(0.79788456 + 0.03567741*x^2)))
__device__ __forceinline__ float gelu_tanh(float x) {
    float u = x * fmaf(0.0356774081f, x * x, 0.7978845608f);
    float t;
    asm("tanh.approx.f32 %0, %1;" : "=f"(t) : "f"(u));
    float hx = 0.5f * x;
    return fmaf(hx, t, hx);
}

__global__ __launch_bounds__(256, 6) void gelu_topk_kernel(
        const float4* __restrict__ x4, float4* __restrict__ out4,
        const float* __restrict__ log_alpha, const float* __restrict__ log_sigma,
        const float4* __restrict__ ema_mean4, const float4* __restrict__ ema_sq4,
        int rows) {
    __shared__ float4  sx[WPB * 256];        // 32 KB: x staged, then gelu
    __shared__ __align__(16) __half2 siv2[512];  // 2 KB: invstd (half2)
    __shared__ __align__(16) __half2 snm2[512];  // 2 KB: -mean*invstd (half2)
    int tid  = threadIdx.x;
    int wib  = tid >> 5;
    int lane = tid & 31;
    int gw   = blockIdx.x * WPB + wib;       // one warp per row

    // ---- issue x prefetch first (DRAM latency overlaps the stats compute) ----
    float4* swarp = sx + wib * 256 + lane;
    if (gw < rows) {
        const float4* xr = x4 + (size_t)gw * (DPAR / 4) + lane;
        #pragma unroll
        for (int c = 0; c < CHUNKS; c++)
            __pipeline_memcpy_async(swarp + c * 32, xr + c * 32, 16);
        __pipeline_commit();
    }

    // ---- per-CTA stats: invstd / -mean*invstd (half2) for 1024 channels ----
    {
        float4 m = __ldg(ema_mean4 + tid);
        float4 q = __ldg(ema_sq4   + tid);
        float ivx = rsqrtf(fmaxf(q.x - m.x * m.x, 1e-6f));
        float ivy = rsqrtf(fmaxf(q.y - m.y * m.y, 1e-6f));
        float ivz = rsqrtf(fmaxf(q.z - m.z * m.z, 1e-6f));
        float ivw = rsqrtf(fmaxf(q.w - m.w * m.w, 1e-6f));
        siv2[2 * tid + 0] = __floats2half2_rn(ivx, ivy);
        siv2[2 * tid + 1] = __floats2half2_rn(ivz, ivw);
        snm2[2 * tid + 0] = __floats2half2_rn(-m.x * ivx, -m.y * ivy);
        snm2[2 * tid + 1] = __floats2half2_rn(-m.z * ivz, -m.w * ivw);
    }
    float alpha = expf(__ldg(log_alpha));
    float sigma = expf(__ldg(log_sigma));
    __syncthreads();
    if (gw >= rows) return;
    __pipeline_wait_prior(0);

    // ---- pass 1: z = |xh*iv + nm| (half2); ungated gelu overwrites x ----
    __half2 z2[H2N];
    __half2 tmaxA = __float2half2_rn(0.0f);
    __half2 tmaxB = __float2half2_rn(0.0f);
    #pragma unroll
    for (int c = 0; c < CHUNKS; c++) {
        int idx = c * 32 + lane;
        float4 xv = swarp[c * 32];
        __half2 xh0 = __floats2half2_rn(xv.x, xv.y);
        __half2 xh1 = __floats2half2_rn(xv.z, xv.w);
        uint2 ivp = *reinterpret_cast<const uint2*>(siv2 + 2 * idx);
        uint2 nmp = *reinterpret_cast<const uint2*>(snm2 + 2 * idx);
        __half2 iv0 = *reinterpret_cast<__half2*>(&ivp.x);
        __half2 iv1 = *reinterpret_cast<__half2*>(&ivp.y);
        __half2 nm0 = *reinterpret_cast<__half2*>(&nmp.x);
        __half2 nm1 = *reinterpret_cast<__half2*>(&nmp.y);
        __half2 za = __habs2(__hfma2(xh0, iv0, nm0));
        __half2 zb = __habs2(__hfma2(xh1, iv1, nm1));
        z2[c * 2 + 0] = za;
        z2[c * 2 + 1] = zb;
        tmaxA = __hmax2(tmaxA, za);
        tmaxB = __hmax2(tmaxB, zb);
        float4 g;                                    // ungated GELU(x)
        g.x = gelu_tanh(xv.x);
        g.y = gelu_tanh(xv.y);
        g.z = gelu_tanh(xv.z);
        g.w = gelu_tanh(xv.w);
        swarp[c * 32] = g;
    }
    __half2 tmax2 = __hmax2(tmaxA, tmaxB);
    float tmax = fmaxf(__low2float(tmax2), __high2float(tmax2));

    // ---- bracket via REDUX on bit patterns (z >= 0) ----
    unsigned tb = __float_as_uint(tmax);
    float hi = __uint_as_float(__reduce_max_sync(0xffffffffu, tb));
    float lo = __uint_as_float(__reduce_min_sync(0xffffffffu, tb));
    float c_lo = 1024.0f, c_hi = 0.0f;

    // ---- count-based bisection, packed half2 compares + REDUX.SUM ----
    #pragma unroll
    for (int it = 0; it < NITER; ++it) {
        float T = 0.5f * (lo + hi);
        __half2 T2 = __float2half2_rn(T);
        __half2 a0 = __float2half2_rn(0.0f), a1 = a0, a2 = a0, a3 = a0;
        #pragma unroll
        for (int i = 0; i < H2N; i += 4) {
            a0 = __hadd2(a0, __hgt2(z2[i + 0], T2));
            a1 = __hadd2(a1, __hgt2(z2[i + 1], T2));
            a2 = __hadd2(a2, __hgt2(z2[i + 2], T2));
            a3 = __hadd2(a3, __hgt2(z2[i + 3], T2));
        }
        __half2 acc = __hadd2(__hadd2(a0, a1), __hadd2(a2, a3));
        int cnt = (int)(__low2float(acc) + __high2float(acc));
        cnt = __reduce_add_sync(0xffffffffu, cnt);
        if (cnt >= KSEL) { lo = T; c_lo = (float)cnt; }
        else             { hi = T; c_hi = (float)cnt; }
    }

    // ---- top-K sum: exact part above hi (count = c_hi known) ----
    __half2 hi2 = __float2half2_rn(hi);
    __half2 s0 = __float2half2_rn(0.0f), s1 = s0, s2 = s0, s3 = s0;
    #pragma unroll
    for (int i = 0; i < H2N; i += 4) {
        s0 = __hfma2(__hgt2(z2[i + 0], hi2), z2[i + 0], s0);
        s1 = __hfma2(__hgt2(z2[i + 1], hi2), z2[i + 1], s1);
        s2 = __hfma2(__hgt2(z2[i + 2], hi2), z2[i + 2], s2);
        s3 = __hfma2(__hgt2(z2[i + 3], hi2), z2[i + 3], s3);
    }
    __half2 sacc = __hadd2(__hadd2(s0, s1), __hadd2(s2, s3));
    float ssum = __low2float(sacc) + __high2float(sacc);
    int ssi = (int)(ssum * 1024.0f);
    ssi = __reduce_add_sync(0xffffffffu, ssi);
    ssum = (float)ssi * (1.0f / 1024.0f);

    // false-position estimate of the K-th order statistic inside [lo,hi]
    float Tk = lo + (hi - lo) * (c_lo - (float)KSEL)
                    * __fdividef(1.0f, fmaxf(c_lo - c_hi, 1.0f));
    Tk = fminf(fmaxf(Tk, lo), hi);

    float surp = (ssum + ((float)KSEL - c_hi) * Tk) * (1.0f / (float)KSEL);
    float gate = 1.0f + alpha * tanhf(sigma * surp);

    // ---- pass 2: out = gate * gelu (LDS + FMUL + STG) ----
    float4* orow = out4 + (size_t)gw * (DPAR / 4) + lane;
    #pragma unroll
    for (int c = 0; c < CHUNKS; c++) {
        float4 gv = swarp[c * 32];
        float4 o;
        o.x = gate * gv.x;
        o.y = gate * gv.y;
        o.z = gate * gv.z;
        o.w = gate * gv.w;
        orow[c * 32] = o;
    }
}

extern "C" void kernel_launch(void* const* d_in, const int* in_sizes, int n_in,
                              void* d_out, int out_size) {
    const float* x         = (const float*)d_in[0];
    const float* log_alpha = (const float*)d_in[1];
    const float* log_sigma = (const float*)d_in[2];
    const float* ema_mean  = (const float*)d_in[3];
    const float* ema_sq    = (const float*)d_in[4];
    float* out = (float*)d_out;

    int d    = in_sizes[3];          // 1024
    int rows = in_sizes[0] / d;      // 32768

    int blocks = (rows + WPB - 1) / WPB;    // 4096
    gelu_topk_kernel<<<blocks, 256>>>(
        reinterpret_cast<const float4*>(x),
        reinterpret_cast<float4*>(out),
        log_alpha, log_sigma,
        reinterpret_cast<const float4*>(ema_mean),
        reinterpret_cast<const float4*>(ema_sq),
        rows);
}